// round 6
// baseline (speedup 1.0000x reference)
#include <cuda_runtime.h>
#include <cuda_bf16.h>
#include <cuda_fp8.h>
#include <cstdint>

// Problem constants
#define BB 4
#define SS 2048
#define DD 1024
#define HH 16
#define HD 64
#define NT (BB * SS)        // 8192 tokens
#define D3 (3 * DD)         // 3072

// fp8 correction scales (powers of two)
#define SC_AHI 32.0f          // 2^5
#define SC_ALO 16384.0f       // 2^14  (= 2^9 * 2^5)
#define SC_BHI 2048.0f        // 2^11
#define SC_BLO 1048576.0f     // 2^20  (= 2^9 * 2^11)
#define DSC    (1.0f / 33554432.0f)   // 2^-25

// ---------------------------------------------------------------------------
// Scratch (device globals — no runtime allocation)
// ---------------------------------------------------------------------------
static __device__ __nv_bfloat16  g_qkvh[(size_t)NT * D3];   // qkv hi/lo bf16 (for attention)
static __device__ __nv_bfloat16  g_qkvl[(size_t)NT * D3];
static __device__ __nv_bfloat16  g_xh[(size_t)NT * DD];     // hidden hi bf16
static __device__ uint8_t        g_xf8[(size_t)NT * 2 * DD];// [lo*2^14 | hi*2^5] e4m3
static __device__ __nv_bfloat16  g_ah[(size_t)NT * DD];     // attn out hi bf16
static __device__ uint8_t        g_af8[(size_t)NT * 2 * DD];
static __device__ __nv_bfloat16  g_wqh[(size_t)D3 * DD];    // c_attn_w^T hi bf16 [N][K]
static __device__ uint8_t        g_wqf8[(size_t)D3 * 2 * DD];// [hi*2^11 | lo*2^20]
static __device__ __nv_bfloat16  g_wph[(size_t)DD * DD];
static __device__ uint8_t        g_wpf8[(size_t)DD * 2 * DD];

// ---------------------------------------------------------------------------
__device__ __forceinline__ uint32_t smem_u32(const void* p) {
    uint32_t a;
    asm("{ .reg .u64 t; cvta.to.shared.u64 t, %1; cvt.u32.u64 %0, t; }" : "=r"(a) : "l"(p));
    return a;
}

#define CP_ASYNC16(saddr, gptr) \
    asm volatile("cp.async.cg.shared.global [%0], [%1], 16;" :: "r"(saddr), "l"(gptr) : "memory")
#define CP_COMMIT()  asm volatile("cp.async.commit_group;" ::: "memory")
#define CP_WAIT0()   asm volatile("cp.async.wait_group 0;" ::: "memory")
#define CP_WAIT1()   asm volatile("cp.async.wait_group 1;" ::: "memory")
#define CP_WAIT2()   asm volatile("cp.async.wait_group 2;" ::: "memory")

#define LDMATRIX_X4(r0, r1, r2, r3, addr) \
    asm volatile("ldmatrix.sync.aligned.m8n8.x4.shared.b16 {%0,%1,%2,%3}, [%4];" \
        : "=r"(r0), "=r"(r1), "=r"(r2), "=r"(r3) : "r"(addr))

#define LDMATRIX_X4_T(r0, r1, r2, r3, addr) \
    asm volatile("ldmatrix.sync.aligned.m8n8.x4.trans.shared.b16 {%0,%1,%2,%3}, [%4];" \
        : "=r"(r0), "=r"(r1), "=r"(r2), "=r"(r3) : "r"(addr))

#define MMA_BF16(c, a, b) \
    asm volatile("mma.sync.aligned.m16n8k16.row.col.f32.bf16.bf16.f32 " \
        "{%0,%1,%2,%3}, {%4,%5,%6,%7}, {%8,%9}, {%0,%1,%2,%3};" \
        : "+f"((c)[0]), "+f"((c)[1]), "+f"((c)[2]), "+f"((c)[3]) \
        : "r"((a)[0]), "r"((a)[1]), "r"((a)[2]), "r"((a)[3]), "r"((b)[0]), "r"((b)[1]))

#define MMA_FP8(c, a, b) \
    asm volatile("mma.sync.aligned.m16n8k32.row.col.f32.e4m3.e4m3.f32 " \
        "{%0,%1,%2,%3}, {%4,%5,%6,%7}, {%8,%9}, {%0,%1,%2,%3};" \
        : "+f"((c)[0]), "+f"((c)[1]), "+f"((c)[2]), "+f"((c)[3]) \
        : "r"((a)[0]), "r"((a)[1]), "r"((a)[2]), "r"((a)[3]), "r"((b)[0]), "r"((b)[1]))

__device__ __forceinline__ uint32_t pack_bf16(float a, float b) {
    __nv_bfloat162 t = __floats2bfloat162_rn(a, b);
    return *reinterpret_cast<uint32_t*>(&t);
}
__device__ __forceinline__ uint8_t f2e4m3(float v) {
    return (uint8_t)__nv_cvt_float_to_fp8(v, __NV_SATFINITE, __NV_E4M3);
}

// ---------------------------------------------------------------------------
// Conversion kernels
// ---------------------------------------------------------------------------
// hidden [M,K] fp32 -> xh bf16 [M,K], xf8 e4m3 [M,2K] = [lo*2^14 | hi*2^5]
__global__ void act_split(const float4* __restrict__ x,
                          uint2* __restrict__ hi, uint8_t* __restrict__ f8,
                          int n4, int K) {
    int i = blockIdx.x * blockDim.x + threadIdx.x;
    if (i >= n4) return;
    const int kq = K >> 2;
    const int row = i / kq, c4 = i % kq;
    float4 v = x[i];
    float vv[4] = {v.x, v.y, v.z, v.w};
    union { uint2 u; __nv_bfloat16 b[4]; } H;
    uchar4 lo8, hi8;
    uint8_t* lop = (uint8_t*)&lo8;
    uint8_t* hip = (uint8_t*)&hi8;
#pragma unroll
    for (int j = 0; j < 4; j++) {
        __nv_bfloat16 h = __float2bfloat16(vv[j]);
        H.b[j] = h;
        const float hf = __bfloat162float(h);
        lop[j] = f2e4m3((vv[j] - hf) * SC_ALO);
        hip[j] = f2e4m3(hf * SC_AHI);
    }
    hi[i] = H.u;
    *(uchar4*)(f8 + (size_t)row * 2 * K + c4 * 4)     = lo8;
    *(uchar4*)(f8 + (size_t)row * 2 * K + K + c4 * 4) = hi8;
}

// W [K,N] fp32 -> Wt hi bf16 [N,K], wf8 e4m3 [N,2K] = [hi*2^11 | lo*2^20]
__global__ void wt_split_t(const float* __restrict__ W,
                           __nv_bfloat16* __restrict__ hi, uint8_t* __restrict__ f8,
                           int K, int N) {
    __shared__ float t[32][33];
    const int kb = blockIdx.y * 32, nb = blockIdx.x * 32;
    const int tx = threadIdx.x, ty = threadIdx.y;
#pragma unroll
    for (int i = 0; i < 32; i += 8)
        t[ty + i][tx] = W[(size_t)(kb + ty + i) * N + nb + tx];
    __syncthreads();
#pragma unroll
    for (int i = 0; i < 32; i += 8) {
        float v = t[tx][ty + i];
        __nv_bfloat16 h = __float2bfloat16(v);
        const float hf = __bfloat162float(h);
        const int n = nb + ty + i, k = kb + tx;
        hi[(size_t)n * K + k] = h;
        f8[(size_t)n * 2 * K + k]     = f2e4m3(hf * SC_BHI);
        f8[(size_t)n * 2 * K + K + k] = f2e4m3((v - hf) * SC_BLO);
    }
}

// ---------------------------------------------------------------------------
// Mixed bf16+fp8 GEMM:
//   C = Ah·Bh^T  +  2^-25 · Af8·Bf8^T  + bias
// Ah [M,K] bf16; Af8 [M,2K] e4m3 ([lo*2^14|hi*2^5]);
// Bh [N,K] bf16; Bf8 [N,2K] e4m3 ([hi*2^11|lo*2^20]).
// 128x128 CTA, 512 threads (4x4 warps, 32x32/warp), 3-stage cp.async.
// ---------------------------------------------------------------------------
#define ROWB 80
#define TILEB (128 * ROWB)            // 10240
#define STAGEB (4 * TILEB)            // 40960
#define GSMEM (3 * STAGEB)            // 122880

extern __shared__ char g_dsmem[];

__global__ void __launch_bounds__(512, 1) gemm_mma(
    const __nv_bfloat16* __restrict__ Ah, const uint8_t* __restrict__ Af8,
    const __nv_bfloat16* __restrict__ Bh, const uint8_t* __restrict__ Bf8,
    const float* __restrict__ bias, float* __restrict__ Cf,
    __nv_bfloat16* __restrict__ Ch, __nv_bfloat16* __restrict__ Cl,
    int M, int N, int K)
{
    const int tid  = threadIdx.x;
    const int wid  = tid >> 5;
    const int lane = tid & 31;
    const int wm   = wid >> 2;        // 0..3
    const int wn   = wid & 3;         // 0..3
    const int bm = blockIdx.y, bn = blockIdx.x;

    const __nv_bfloat16* Abh = Ah  + (size_t)(bm * 128) * K;
    const uint8_t*       Abf = Af8 + (size_t)(bm * 128) * 2 * K;
    const __nv_bfloat16* Bbh = Bh  + (size_t)(bn * 128) * K;
    const uint8_t*       Bbf = Bf8 + (size_t)(bn * 128) * 2 * K;

    const uint32_t sb = smem_u32(g_dsmem);

    float accm[2][4][4], accc[2][4][4];
#pragma unroll
    for (int i = 0; i < 2; i++)
#pragma unroll
        for (int j = 0; j < 4; j++)
#pragma unroll
            for (int v = 0; v < 4; v++) { accm[i][j][v] = 0.0f; accc[i][j][v] = 0.0f; }

    const int NS = K >> 5;            // 32 stages, 32 bf16-k / 64 fp8-k' each

    const int ld_r = tid >> 2;        // 0..127
    const int ld_c = tid & 3;         // 0..3
    auto load_stage = [&](int s, int buf) {
        const uint32_t base = sb + buf * STAGEB + ld_r * ROWB + ld_c * 16;
        // bf16 tiles (T0=Ah, T2=Bh): 16B = 8 bf16 at k = s*32 + ld_c*8
        const size_t gh = (size_t)ld_r * K + s * 32 + ld_c * 8;
        CP_ASYNC16(base,             Abh + gh);
        CP_ASYNC16(base + 2 * TILEB, Bbh + gh);
        // fp8 tiles (T1=Af8, T3=Bf8): 16B at byte k' = s*64 + ld_c*16
        const size_t gf = (size_t)ld_r * 2 * K + s * 64 + ld_c * 16;
        CP_ASYNC16(base + TILEB,     Abf + gf);
        CP_ASYNC16(base + 3 * TILEB, Bbf + gf);
        CP_COMMIT();
    };

    load_stage(0, 0);
    load_stage(1, 1);
    load_stage(2, 2);

    const int a_row  = (lane & 15);
    const int a_koff = (lane >> 4) * 16;
    const int b_blk  = lane >> 3;
    const int b_row8 = lane & 7;
    const int b_noff = ((b_blk >> 1) << 3) + b_row8;
    const int b_koff = (b_blk & 1) * 16;

    int buf = 0;
    for (int s = 0; s < NS; s++) {
        if (s <= NS - 3)      CP_WAIT2();
        else if (s == NS - 2) CP_WAIT1();
        else                  CP_WAIT0();
        __syncthreads();

        const uint32_t st = sb + buf * STAGEB;
#pragma unroll
        for (int ks = 0; ks < 2; ks++) {
            const int kb = ks * 32;   // 32B = one k16 bf16 step / one k32 fp8 step

            // ---- bf16 main term ----
            uint32_t ah[2][4], bh[4][2];
#pragma unroll
            for (int mt = 0; mt < 2; mt++) {
                const uint32_t ar = st + (wm * 32 + mt * 16 + a_row) * ROWB + kb + a_koff;
                LDMATRIX_X4(ah[mt][0], ah[mt][1], ah[mt][2], ah[mt][3], ar);
            }
#pragma unroll
            for (int p = 0; p < 2; p++) {
                const uint32_t br = st + 2 * TILEB +
                    (wn * 32 + p * 16 + b_noff) * ROWB + kb + b_koff;
                LDMATRIX_X4(bh[2 * p][0], bh[2 * p][1], bh[2 * p + 1][0], bh[2 * p + 1][1], br);
            }
#pragma unroll
            for (int mt = 0; mt < 2; mt++)
#pragma unroll
                for (int nt = 0; nt < 4; nt++)
                    MMA_BF16(accm[mt][nt], ah[mt], bh[nt]);

            // ---- fp8 correction term (k32 per step) ----
            uint32_t af[2][4], bf[4][2];
#pragma unroll
            for (int mt = 0; mt < 2; mt++) {
                const uint32_t ar = st + TILEB + (wm * 32 + mt * 16 + a_row) * ROWB + kb + a_koff;
                LDMATRIX_X4(af[mt][0], af[mt][1], af[mt][2], af[mt][3], ar);
            }
#pragma unroll
            for (int p = 0; p < 2; p++) {
                const uint32_t br = st + 3 * TILEB +
                    (wn * 32 + p * 16 + b_noff) * ROWB + kb + b_koff;
                LDMATRIX_X4(bf[2 * p][0], bf[2 * p][1], bf[2 * p + 1][0], bf[2 * p + 1][1], br);
            }
#pragma unroll
            for (int mt = 0; mt < 2; mt++)
#pragma unroll
                for (int nt = 0; nt < 4; nt++)
                    MMA_FP8(accc[mt][nt], af[mt], bf[nt]);
        }
        __syncthreads();
        if (s + 3 < NS) load_stage(s + 3, buf);
        buf = (buf == 2) ? 0 : buf + 1;
    }

    const int r0 = bm * 128 + wm * 32 + (lane >> 2);
    const int c0 = bn * 128 + wn * 32 + (lane & 3) * 2;
    if (Cf) {
#pragma unroll
        for (int mt = 0; mt < 2; mt++)
#pragma unroll
            for (int nt = 0; nt < 4; nt++) {
                const int row = r0 + mt * 16;
                const int col = c0 + nt * 8;
                float2 o0, o1;
                o0.x = accm[mt][nt][0] + accc[mt][nt][0] * DSC + bias[col];
                o0.y = accm[mt][nt][1] + accc[mt][nt][1] * DSC + bias[col + 1];
                o1.x = accm[mt][nt][2] + accc[mt][nt][2] * DSC + bias[col];
                o1.y = accm[mt][nt][3] + accc[mt][nt][3] * DSC + bias[col + 1];
                *(float2*)(Cf + (size_t)row * N + col) = o0;
                *(float2*)(Cf + (size_t)(row + 8) * N + col) = o1;
            }
    } else {
#pragma unroll
        for (int mt = 0; mt < 2; mt++)
#pragma unroll
            for (int nt = 0; nt < 4; nt++) {
                const int row = r0 + mt * 16;
                const int col = c0 + nt * 8;
                const float b0 = bias[col], b1 = bias[col + 1];
#pragma unroll
                for (int hf = 0; hf < 2; hf++) {
                    const float v0 = accm[mt][nt][2 * hf]     + accc[mt][nt][2 * hf]     * DSC + b0;
                    const float v1 = accm[mt][nt][2 * hf + 1] + accc[mt][nt][2 * hf + 1] * DSC + b1;
                    const float h0 = __bfloat162float(__float2bfloat16(v0));
                    const float h1 = __bfloat162float(__float2bfloat16(v1));
                    const size_t off = (size_t)(row + 8 * hf) * N + col;
                    *(uint32_t*)(Ch + off) = pack_bf16(h0, h1);
                    *(uint32_t*)(Cl + off) = pack_bf16(v0 - h0, v1 - h1);
                }
            }
    }
}

// ---------------------------------------------------------------------------
// Tensor-core causal flash attention (bf16 3-term, unchanged math).
// Epilogue now also emits the fp8 correction operand for the proj GEMM.
// ---------------------------------------------------------------------------
#define AROWB 144
#define ATILE (64 * AROWB)
#define ASTAGE (4 * ATILE)
#define ASMEM (2 * ASTAGE)

__global__ void __launch_bounds__(256) attn_mma(
    const __nv_bfloat16* __restrict__ QKVh, const __nv_bfloat16* __restrict__ QKVl,
    __nv_bfloat16* __restrict__ Oh, uint8_t* __restrict__ Of8)
{
    const int tid  = threadIdx.x;
    const int wid  = tid >> 5;
    const int lane = tid & 31;
    const int qtile = (gridDim.x - 1) - blockIdx.x;
    const int bh = blockIdx.y;
    const int b  = bh >> 4;
    const int h  = bh & 15;
    const int bS = b * SS;
    const int qbase = qtile * 128 + wid * 16;

    const uint32_t sb = smem_u32(g_dsmem);

#pragma unroll
    for (int i = 0; i < 4; i++) {
        const int idx = i * 256 + tid;
        const int r = idx >> 3, c = idx & 7;
        const size_t g = (size_t)(bS + qtile * 128 + r) * D3 + h * HD + c * 8;
        CP_ASYNC16(sb + r * AROWB + c * 16, QKVh + g);
        CP_ASYNC16(sb + 128 * AROWB + r * AROWB + c * 16, QKVl + g);
    }
    CP_COMMIT();
    CP_WAIT0();
    __syncthreads();

    uint32_t qh[4][4], ql[4][4];
    const int a_row  = lane & 15;
    const int a_koff = (lane >> 4) * 16;
    {
        const uint32_t qr = sb + (wid * 16 + a_row) * AROWB + a_koff;
#pragma unroll
        for (int ks = 0; ks < 4; ks++) {
            LDMATRIX_X4(qh[ks][0], qh[ks][1], qh[ks][2], qh[ks][3], qr + ks * 32);
            LDMATRIX_X4(ql[ks][0], ql[ks][1], ql[ks][2], ql[ks][3],
                        qr + 128 * AROWB + ks * 32);
        }
    }
    __syncthreads();

    auto load_kv = [&](int kt, int buf) {
        const int k0 = kt * 64;
        const uint32_t base = sb + buf * ASTAGE;
#pragma unroll
        for (int i = 0; i < 8; i++) {
            const int idx  = i * 256 + tid;
            const int tile = idx >> 9;
            const int r    = (idx >> 3) & 63;
            const int c    = idx & 7;
            const size_t g = (size_t)(bS + k0 + r) * D3 +
                             ((tile < 2) ? DD : 2 * DD) + h * HD + c * 8;
            const __nv_bfloat16* src = (tile & 1) ? QKVl : QKVh;
            CP_ASYNC16(base + tile * ATILE + r * AROWB + c * 16, src + g);
        }
        CP_COMMIT();
    };

    float o[8][4];
#pragma unroll
    for (int n = 0; n < 8; n++)
#pragma unroll
        for (int j = 0; j < 4; j++) o[n][j] = 0.0f;
    float mrow[2] = {-1e30f, -1e30f};
    float lrow[2] = {0.0f, 0.0f};

    const int b_blk  = lane >> 3;
    const int b_row8 = lane & 7;
    const int b_noff = ((b_blk >> 1) << 3) + b_row8;
    const int b_koff = (b_blk & 1) * 16;
    const int v_row  = lane & 15;
    const int v_coff = ((lane >> 4) & 1) * 16;

    const int ntl = 2 * qtile + 2;
    load_kv(0, 0);

    for (int kt = 0; kt < ntl; kt++) {
        const int buf = kt & 1;
        const int k0 = kt * 64;
        if (kt + 1 < ntl) { load_kv(kt + 1, buf ^ 1); CP_WAIT1(); }
        else              { CP_WAIT0(); }
        __syncthreads();

        if (k0 <= qbase + 15) {
            const uint32_t kbse = sb + buf * ASTAGE;
            const uint32_t vbse = kbse + 2 * ATILE;

            float s[8][4];
#pragma unroll
            for (int n = 0; n < 8; n++)
#pragma unroll
                for (int j = 0; j < 4; j++) s[n][j] = 0.0f;

#pragma unroll
            for (int p = 0; p < 4; p++) {
#pragma unroll
                for (int ks = 0; ks < 4; ks++) {
                    uint32_t kh[4], kl[4];
                    const uint32_t ar = kbse + (p * 16 + b_noff) * AROWB + ks * 32 + b_koff;
                    LDMATRIX_X4(kh[0], kh[1], kh[2], kh[3], ar);
                    LDMATRIX_X4(kl[0], kl[1], kl[2], kl[3], ar + ATILE);
                    uint32_t bh0[2] = {kh[0], kh[1]}, bh1[2] = {kh[2], kh[3]};
                    uint32_t bl0[2] = {kl[0], kl[1]}, bl1[2] = {kl[2], kl[3]};
                    MMA_BF16(s[2 * p],     qh[ks], bh0);
                    MMA_BF16(s[2 * p],     ql[ks], bh0);
                    MMA_BF16(s[2 * p],     qh[ks], bl0);
                    MMA_BF16(s[2 * p + 1], qh[ks], bh1);
                    MMA_BF16(s[2 * p + 1], ql[ks], bh1);
                    MMA_BF16(s[2 * p + 1], qh[ks], bl1);
                }
            }

            const bool need_mask = (k0 + 63 > qbase);
            const int row0 = qbase + (lane >> 2);
            const int colb = k0 + (lane & 3) * 2;
#pragma unroll
            for (int hf = 0; hf < 2; hf++) {
                const int row = row0 + 8 * hf;
                float mx = mrow[hf];
#pragma unroll
                for (int n = 0; n < 8; n++) {
                    float v0 = s[n][2 * hf]     * 0.125f;
                    float v1 = s[n][2 * hf + 1] * 0.125f;
                    if (need_mask) {
                        const int col = colb + 8 * n;
                        if (col > row)     v0 = -1e30f;
                        if (col + 1 > row) v1 = -1e30f;
                    }
                    s[n][2 * hf] = v0; s[n][2 * hf + 1] = v1;
                    mx = fmaxf(mx, fmaxf(v0, v1));
                }
                mx = fmaxf(mx, __shfl_xor_sync(0xffffffffu, mx, 1));
                mx = fmaxf(mx, __shfl_xor_sync(0xffffffffu, mx, 2));
                const float alpha = __expf(mrow[hf] - mx);
                lrow[hf] *= alpha;
#pragma unroll
                for (int n = 0; n < 8; n++) {
                    o[n][2 * hf]     *= alpha;
                    o[n][2 * hf + 1] *= alpha;
                }
                float ls = 0.0f;
#pragma unroll
                for (int n = 0; n < 8; n++) {
                    const float p0 = __expf(s[n][2 * hf]     - mx);
                    const float p1 = __expf(s[n][2 * hf + 1] - mx);
                    s[n][2 * hf] = p0; s[n][2 * hf + 1] = p1;
                    ls += p0 + p1;
                }
                lrow[hf] += ls;
                mrow[hf] = mx;
            }

#pragma unroll
            for (int ks = 0; ks < 4; ks++) {
                uint32_t ph[4], pl[4];
#pragma unroll
                for (int q2 = 0; q2 < 2; q2++) {
                    const float* pv = s[2 * ks + q2];
#pragma unroll
                    for (int e = 0; e < 2; e++) {
                        const float v0 = pv[2 * e], v1 = pv[2 * e + 1];
                        const float h0 = __bfloat162float(__float2bfloat16(v0));
                        const float h1 = __bfloat162float(__float2bfloat16(v1));
                        ph[q2 * 2 + e] = pack_bf16(h0, h1);
                        pl[q2 * 2 + e] = pack_bf16(v0 - h0, v1 - h1);
                    }
                }
#pragma unroll
                for (int np = 0; np < 4; np++) {
                    uint32_t vh[4], vl[4];
                    const uint32_t va = vbse + (ks * 16 + v_row) * AROWB + np * 32 + v_coff;
                    LDMATRIX_X4_T(vh[0], vh[1], vh[2], vh[3], va);
                    LDMATRIX_X4_T(vl[0], vl[1], vl[2], vl[3], va + ATILE);
                    uint32_t vh0[2] = {vh[0], vh[1]}, vh1[2] = {vh[2], vh[3]};
                    uint32_t vl0[2] = {vl[0], vl[1]}, vl1[2] = {vl[2], vl[3]};
                    MMA_BF16(o[2 * np],     ph, vh0);
                    MMA_BF16(o[2 * np],     pl, vh0);
                    MMA_BF16(o[2 * np],     ph, vl0);
                    MMA_BF16(o[2 * np + 1], ph, vh1);
                    MMA_BF16(o[2 * np + 1], pl, vh1);
                    MMA_BF16(o[2 * np + 1], ph, vl1);
                }
            }
        }
        __syncthreads();
    }

    float inv[2];
#pragma unroll
    for (int hf = 0; hf < 2; hf++) {
        float l = lrow[hf];
        l += __shfl_xor_sync(0xffffffffu, l, 1);
        l += __shfl_xor_sync(0xffffffffu, l, 2);
        inv[hf] = 1.0f / l;
    }
    const int row0 = qbase + (lane >> 2);
    const int colb = h * HD + (lane & 3) * 2;
#pragma unroll
    for (int hf = 0; hf < 2; hf++) {
        const size_t rof  = (size_t)(bS + row0 + 8 * hf) * DD;
        const size_t rof8 = (size_t)(bS + row0 + 8 * hf) * 2 * DD;
#pragma unroll
        for (int n = 0; n < 8; n++) {
            const float v0 = o[n][2 * hf]     * inv[hf];
            const float v1 = o[n][2 * hf + 1] * inv[hf];
            const float h0 = __bfloat162float(__float2bfloat16(v0));
            const float h1 = __bfloat162float(__float2bfloat16(v1));
            const size_t off = rof + colb + n * 8;
            *(uint32_t*)(Oh + off) = pack_bf16(h0, h1);
            const uint16_t lo16 = (uint16_t)f2e4m3((v0 - h0) * SC_ALO)
                                | ((uint16_t)f2e4m3((v1 - h1) * SC_ALO) << 8);
            const uint16_t hi16 = (uint16_t)f2e4m3(h0 * SC_AHI)
                                | ((uint16_t)f2e4m3(h1 * SC_AHI) << 8);
            *(uint16_t*)(Of8 + rof8 + colb + n * 8)      = lo16;
            *(uint16_t*)(Of8 + rof8 + DD + colb + n * 8) = hi16;
        }
    }
}

// ---------------------------------------------------------------------------
extern "C" void kernel_launch(void* const* d_in, const int* in_sizes, int n_in,
                              void* d_out, int out_size)
{
    const float* hidden   = (const float*)d_in[0];
    const float* c_attn_w = (const float*)d_in[1];
    const float* c_attn_b = (const float*)d_in[2];
    const float* c_proj_w = (const float*)d_in[3];
    const float* c_proj_b = (const float*)d_in[4];
    float* out = (float*)d_out;

    __nv_bfloat16 *qkvh, *qkvl, *xh, *ah, *wqh, *wph;
    uint8_t *xf8, *af8, *wqf8, *wpf8;
    cudaGetSymbolAddress((void**)&qkvh, g_qkvh);
    cudaGetSymbolAddress((void**)&qkvl, g_qkvl);
    cudaGetSymbolAddress((void**)&xh,   g_xh);
    cudaGetSymbolAddress((void**)&xf8,  g_xf8);
    cudaGetSymbolAddress((void**)&ah,   g_ah);
    cudaGetSymbolAddress((void**)&af8,  g_af8);
    cudaGetSymbolAddress((void**)&wqh,  g_wqh);
    cudaGetSymbolAddress((void**)&wqf8, g_wqf8);
    cudaGetSymbolAddress((void**)&wph,  g_wph);
    cudaGetSymbolAddress((void**)&wpf8, g_wpf8);

    cudaFuncSetAttribute(gemm_mma, cudaFuncAttributeMaxDynamicSharedMemorySize, GSMEM);
    cudaFuncSetAttribute(attn_mma, cudaFuncAttributeMaxDynamicSharedMemorySize, ASMEM);

    wt_split_t<<<dim3(D3 / 32, DD / 32), dim3(32, 8)>>>(c_attn_w, wqh, wqf8, DD, D3);
    wt_split_t<<<dim3(DD / 32, DD / 32), dim3(32, 8)>>>(c_proj_w, wph, wpf8, DD, DD);

    {
        const int n4 = NT * DD / 4;
        act_split<<<(n4 + 255) / 256, 256>>>((const float4*)hidden, (uint2*)xh, xf8, n4, DD);
    }

    // 1) QKV projection (bf16 main + fp8 correction) -> bf16 hi/lo for attention
    gemm_mma<<<dim3(D3 / 128, NT / 128), 512, GSMEM>>>(
        xh, xf8, wqh, wqf8, c_attn_b, nullptr, qkvh, qkvl, NT, D3, DD);

    // 2) tensor-core causal flash attention -> ah bf16 + af8 correction operand
    attn_mma<<<dim3(SS / 128, BB * HH), 256, ASMEM>>>(qkvh, qkvl, ah, af8);

    // 3) output projection -> fp32
    gemm_mma<<<dim3(DD / 128, NT / 128), 512, GSMEM>>>(
        ah, af8, wph, wpf8, c_proj_b, out, nullptr, nullptr, NT, DD, DD);
}

// round 7
// speedup vs baseline: 2.2986x; 2.2986x over previous
#include <cuda_runtime.h>
#include <cuda_fp16.h>
#include <cstdint>

// Problem constants
#define BB 4
#define SS 2048
#define DD 1024
#define HH 16
#define HD 64
#define NT (BB * SS)        // 8192 tokens
#define D3 (3 * DD)         // 3072

#define WSC 64.0f           // weight scale 2^6 (keeps f16 weights normal)
#define IWSC (1.0f / 64.0f)

// ---------------------------------------------------------------------------
// Scratch (device globals — no runtime allocation)
// ---------------------------------------------------------------------------
static __device__ __half g_qkv[(size_t)NT * D3];   // qkv f16
static __device__ __half g_x  [(size_t)NT * DD];   // hidden f16
static __device__ __half g_a  [(size_t)NT * DD];   // attn out f16
static __device__ __half g_wq [(size_t)D3 * DD];   // c_attn_w^T f16 *64  [N][K]
static __device__ __half g_wp [(size_t)DD * DD];   // c_proj_w^T f16 *64

// ---------------------------------------------------------------------------
__device__ __forceinline__ uint32_t smem_u32(const void* p) {
    uint32_t a;
    asm("{ .reg .u64 t; cvta.to.shared.u64 t, %1; cvt.u32.u64 %0, t; }" : "=r"(a) : "l"(p));
    return a;
}

#define CP_ASYNC16(saddr, gptr) \
    asm volatile("cp.async.cg.shared.global [%0], [%1], 16;" :: "r"(saddr), "l"(gptr) : "memory")
#define CP_COMMIT()  asm volatile("cp.async.commit_group;" ::: "memory")
#define CP_WAIT0()   asm volatile("cp.async.wait_group 0;" ::: "memory")
#define CP_WAIT1()   asm volatile("cp.async.wait_group 1;" ::: "memory")
#define CP_WAIT2()   asm volatile("cp.async.wait_group 2;" ::: "memory")

#define LDMATRIX_X4(r0, r1, r2, r3, addr) \
    asm volatile("ldmatrix.sync.aligned.m8n8.x4.shared.b16 {%0,%1,%2,%3}, [%4];" \
        : "=r"(r0), "=r"(r1), "=r"(r2), "=r"(r3) : "r"(addr))

#define LDMATRIX_X4_T(r0, r1, r2, r3, addr) \
    asm volatile("ldmatrix.sync.aligned.m8n8.x4.trans.shared.b16 {%0,%1,%2,%3}, [%4];" \
        : "=r"(r0), "=r"(r1), "=r"(r2), "=r"(r3) : "r"(addr))

#define MMA_F16(c, a, b) \
    asm volatile("mma.sync.aligned.m16n8k16.row.col.f32.f16.f16.f32 " \
        "{%0,%1,%2,%3}, {%4,%5,%6,%7}, {%8,%9}, {%0,%1,%2,%3};" \
        : "+f"((c)[0]), "+f"((c)[1]), "+f"((c)[2]), "+f"((c)[3]) \
        : "r"((a)[0]), "r"((a)[1]), "r"((a)[2]), "r"((a)[3]), "r"((b)[0]), "r"((b)[1]))

__device__ __forceinline__ uint32_t pack_f16(float a, float b) {
    __half2 t = __floats2half2_rn(a, b);
    return *reinterpret_cast<uint32_t*>(&t);
}

// ---------------------------------------------------------------------------
// Conversion kernels
// ---------------------------------------------------------------------------
__global__ void act_h(const float4* __restrict__ x, uint2* __restrict__ o, int n4) {
    int i = blockIdx.x * blockDim.x + threadIdx.x;
    if (i >= n4) return;
    float4 v = x[i];
    uint2 r;
    r.x = pack_f16(v.x, v.y);
    r.y = pack_f16(v.z, v.w);
    o[i] = r;
}

// W [K,N] fp32 -> Wt [N,K] f16, scaled by 64
__global__ void wt_h(const float* __restrict__ W, __half* __restrict__ o, int K, int N) {
    __shared__ float t[32][33];
    const int kb = blockIdx.y * 32, nb = blockIdx.x * 32;
    const int tx = threadIdx.x, ty = threadIdx.y;
#pragma unroll
    for (int i = 0; i < 32; i += 8)
        t[ty + i][tx] = W[(size_t)(kb + ty + i) * N + nb + tx];
    __syncthreads();
#pragma unroll
    for (int i = 0; i < 32; i += 8)
        o[(size_t)(nb + ty + i) * K + kb + tx] = __float2half_rn(t[tx][ty + i] * WSC);
}

// ---------------------------------------------------------------------------
// f16 HMMA GEMM: C[M,N] = A[M,K] @ (B[N,K])^T * (1/64) + bias
// 256x128 CTA tile, 512 threads (4x4 warps, 64x32 each), BK=32,
// 3-stage cp.async pipeline. Output fp32 (Cf) or f16 (Ch).
// ---------------------------------------------------------------------------
#define ROWB 80
#define ATILEB (256 * ROWB)           // 20480
#define BTILEB (128 * ROWB)           // 10240
#define STAGEB (ATILEB + BTILEB)      // 30720
#define GSMEM (3 * STAGEB)            // 92160

extern __shared__ char g_dsmem[];

__global__ void __launch_bounds__(512, 1) gemm_mma(
    const __half* __restrict__ A, const __half* __restrict__ B,
    const float* __restrict__ bias, float* __restrict__ Cf,
    __half* __restrict__ Ch, int M, int N, int K)
{
    const int tid  = threadIdx.x;
    const int wid  = tid >> 5;
    const int lane = tid & 31;
    const int wm   = wid >> 2;        // 0..3
    const int wn   = wid & 3;         // 0..3
    const int bm = blockIdx.y, bn = blockIdx.x;

    const __half* Ab = A + (size_t)(bm * 256) * K;
    const __half* Bb = B + (size_t)(bn * 128) * K;

    const uint32_t sb = smem_u32(g_dsmem);

    float acc[4][4][4];
#pragma unroll
    for (int i = 0; i < 4; i++)
#pragma unroll
        for (int j = 0; j < 4; j++)
#pragma unroll
            for (int v = 0; v < 4; v++) acc[i][j][v] = 0.0f;

    const int NS = K >> 5;            // 32

    // stage = 1536 x 16B chunks: 1024 for A (256 rows x 4), 512 for B
    auto load_stage = [&](int s, int buf) {
        const int k0 = s << 5;
        const uint32_t base = sb + buf * STAGEB;
#pragma unroll
        for (int i = 0; i < 3; i++) {
            const int idx = i * 512 + tid;
            if (idx < 1024) {
                const int r = idx >> 2, c = idx & 3;
                CP_ASYNC16(base + r * ROWB + c * 16, Ab + (size_t)r * K + k0 + c * 8);
            } else {
                const int j = idx - 1024;
                const int r = j >> 2, c = j & 3;
                CP_ASYNC16(base + ATILEB + r * ROWB + c * 16, Bb + (size_t)r * K + k0 + c * 8);
            }
        }
        CP_COMMIT();
    };

    load_stage(0, 0);
    load_stage(1, 1);
    load_stage(2, 2);

    const int a_row  = (lane & 15);
    const int a_koff = (lane >> 4) * 16;
    const int b_blk  = lane >> 3;
    const int b_row8 = lane & 7;
    const int b_noff = ((b_blk >> 1) << 3) + b_row8;
    const int b_koff = (b_blk & 1) * 16;

    int buf = 0;
    for (int s = 0; s < NS; s++) {
        if (s <= NS - 3)      CP_WAIT2();
        else if (s == NS - 2) CP_WAIT1();
        else                  CP_WAIT0();
        __syncthreads();

        const uint32_t st = sb + buf * STAGEB;
#pragma unroll
        for (int ks = 0; ks < 2; ks++) {
            const int kb = ks * 32;

            uint32_t af[4][4], bf[4][2];
#pragma unroll
            for (int mt = 0; mt < 4; mt++) {
                const uint32_t ar = st + (wm * 64 + mt * 16 + a_row) * ROWB + kb + a_koff;
                LDMATRIX_X4(af[mt][0], af[mt][1], af[mt][2], af[mt][3], ar);
            }
#pragma unroll
            for (int p = 0; p < 2; p++) {
                const uint32_t br = st + ATILEB +
                    (wn * 32 + p * 16 + b_noff) * ROWB + kb + b_koff;
                LDMATRIX_X4(bf[2 * p][0], bf[2 * p][1], bf[2 * p + 1][0], bf[2 * p + 1][1], br);
            }
#pragma unroll
            for (int mt = 0; mt < 4; mt++)
#pragma unroll
                for (int nt = 0; nt < 4; nt++)
                    MMA_F16(acc[mt][nt], af[mt], bf[nt]);
        }
        __syncthreads();
        if (s + 3 < NS) load_stage(s + 3, buf);
        buf = (buf == 2) ? 0 : buf + 1;
    }

    const int r0 = bm * 256 + wm * 64 + (lane >> 2);
    const int c0 = bn * 128 + wn * 32 + (lane & 3) * 2;
    if (Cf) {
#pragma unroll
        for (int mt = 0; mt < 4; mt++)
#pragma unroll
            for (int nt = 0; nt < 4; nt++) {
                const int row = r0 + mt * 16;
                const int col = c0 + nt * 8;
                float2 o0, o1;
                o0.x = acc[mt][nt][0] * IWSC + bias[col];
                o0.y = acc[mt][nt][1] * IWSC + bias[col + 1];
                o1.x = acc[mt][nt][2] * IWSC + bias[col];
                o1.y = acc[mt][nt][3] * IWSC + bias[col + 1];
                *(float2*)(Cf + (size_t)row * N + col) = o0;
                *(float2*)(Cf + (size_t)(row + 8) * N + col) = o1;
            }
    } else {
#pragma unroll
        for (int mt = 0; mt < 4; mt++)
#pragma unroll
            for (int nt = 0; nt < 4; nt++) {
                const int row = r0 + mt * 16;
                const int col = c0 + nt * 8;
                const float b0 = bias[col], b1 = bias[col + 1];
                *(uint32_t*)(Ch + (size_t)row * N + col) =
                    pack_f16(acc[mt][nt][0] * IWSC + b0, acc[mt][nt][1] * IWSC + b1);
                *(uint32_t*)(Ch + (size_t)(row + 8) * N + col) =
                    pack_f16(acc[mt][nt][2] * IWSC + b0, acc[mt][nt][3] * IWSC + b1);
            }
    }
}

// ---------------------------------------------------------------------------
// Tensor-core causal flash attention, pure f16 operands, fp32 softmax/accum.
// CTA: 128 q rows of one (b,h); 8 warps x 16 rows; 64-key K/V tiles,
// double-buffered cp.async.
// ---------------------------------------------------------------------------
#define AROWB 144
#define ATILE (64 * AROWB)            // 9216
#define ASTAGE (2 * ATILE)            // K|V = 18432
#define ASMEM (2 * ASTAGE)            // 36864

__global__ void __launch_bounds__(256) attn_mma(
    const __half* __restrict__ QKV, __half* __restrict__ O)
{
    const int tid  = threadIdx.x;
    const int wid  = tid >> 5;
    const int lane = tid & 31;
    const int qtile = (gridDim.x - 1) - blockIdx.x;   // heavy tiles first
    const int bh = blockIdx.y;
    const int b  = bh >> 4;
    const int h  = bh & 15;
    const int bS = b * SS;
    const int qbase = qtile * 128 + wid * 16;

    const uint32_t sb = smem_u32(g_dsmem);

    // stage Q (128 rows x 64 dims f16) into smem
#pragma unroll
    for (int i = 0; i < 4; i++) {
        const int idx = i * 256 + tid;          // 0..1023
        const int r = idx >> 3, c = idx & 7;
        const size_t g = (size_t)(bS + qtile * 128 + r) * D3 + h * HD + c * 8;
        CP_ASYNC16(sb + r * AROWB + c * 16, QKV + g);
    }
    CP_COMMIT();
    CP_WAIT0();
    __syncthreads();

    uint32_t qf[4][4];
    const int a_row  = lane & 15;
    const int a_koff = (lane >> 4) * 16;
    {
        const uint32_t qr = sb + (wid * 16 + a_row) * AROWB + a_koff;
#pragma unroll
        for (int ks = 0; ks < 4; ks++)
            LDMATRIX_X4(qf[ks][0], qf[ks][1], qf[ks][2], qf[ks][3], qr + ks * 32);
    }
    __syncthreads();   // Q region about to be reused for K/V

    auto load_kv = [&](int kt, int buf) {
        const int k0 = kt * 64;
        const uint32_t base = sb + buf * ASTAGE;
#pragma unroll
        for (int i = 0; i < 4; i++) {
            const int idx  = i * 256 + tid;     // 0..1023
            const int tile = idx >> 9;          // 0=K, 1=V
            const int r    = (idx >> 3) & 63;
            const int c    = idx & 7;
            const size_t g = (size_t)(bS + k0 + r) * D3 +
                             (tile ? 2 * DD : DD) + h * HD + c * 8;
            CP_ASYNC16(base + tile * ATILE + r * AROWB + c * 16, QKV + g);
        }
        CP_COMMIT();
    };

    float o[8][4];
#pragma unroll
    for (int n = 0; n < 8; n++)
#pragma unroll
        for (int j = 0; j < 4; j++) o[n][j] = 0.0f;
    float mrow[2] = {-1e30f, -1e30f};
    float lrow[2] = {0.0f, 0.0f};

    const int b_blk  = lane >> 3;
    const int b_row8 = lane & 7;
    const int b_noff = ((b_blk >> 1) << 3) + b_row8;
    const int b_koff = (b_blk & 1) * 16;
    const int v_row  = lane & 15;
    const int v_coff = ((lane >> 4) & 1) * 16;

    const int ntl = 2 * qtile + 2;
    load_kv(0, 0);

    for (int kt = 0; kt < ntl; kt++) {
        const int buf = kt & 1;
        const int k0 = kt * 64;
        if (kt + 1 < ntl) { load_kv(kt + 1, buf ^ 1); CP_WAIT1(); }
        else              { CP_WAIT0(); }
        __syncthreads();

        if (k0 <= qbase + 15) {
            const uint32_t kbse = sb + buf * ASTAGE;
            const uint32_t vbse = kbse + ATILE;

            // S = Q K^T
            float s[8][4];
#pragma unroll
            for (int n = 0; n < 8; n++)
#pragma unroll
                for (int j = 0; j < 4; j++) s[n][j] = 0.0f;

#pragma unroll
            for (int p = 0; p < 4; p++) {
#pragma unroll
                for (int ks = 0; ks < 4; ks++) {
                    uint32_t kf[4];
                    const uint32_t ar = kbse + (p * 16 + b_noff) * AROWB + ks * 32 + b_koff;
                    LDMATRIX_X4(kf[0], kf[1], kf[2], kf[3], ar);
                    uint32_t b0[2] = {kf[0], kf[1]}, b1[2] = {kf[2], kf[3]};
                    MMA_F16(s[2 * p],     qf[ks], b0);
                    MMA_F16(s[2 * p + 1], qf[ks], b1);
                }
            }

            // masking + online softmax
            const bool need_mask = (k0 + 63 > qbase);
            const int row0 = qbase + (lane >> 2);
            const int colb = k0 + (lane & 3) * 2;
#pragma unroll
            for (int hf = 0; hf < 2; hf++) {
                const int row = row0 + 8 * hf;
                float mx = mrow[hf];
#pragma unroll
                for (int n = 0; n < 8; n++) {
                    float v0 = s[n][2 * hf]     * 0.125f;
                    float v1 = s[n][2 * hf + 1] * 0.125f;
                    if (need_mask) {
                        const int col = colb + 8 * n;
                        if (col > row)     v0 = -1e30f;
                        if (col + 1 > row) v1 = -1e30f;
                    }
                    s[n][2 * hf] = v0; s[n][2 * hf + 1] = v1;
                    mx = fmaxf(mx, fmaxf(v0, v1));
                }
                mx = fmaxf(mx, __shfl_xor_sync(0xffffffffu, mx, 1));
                mx = fmaxf(mx, __shfl_xor_sync(0xffffffffu, mx, 2));
                const float alpha = __expf(mrow[hf] - mx);
                lrow[hf] *= alpha;
#pragma unroll
                for (int n = 0; n < 8; n++) {
                    o[n][2 * hf]     *= alpha;
                    o[n][2 * hf + 1] *= alpha;
                }
                float ls = 0.0f;
#pragma unroll
                for (int n = 0; n < 8; n++) {
                    const float p0 = __expf(s[n][2 * hf]     - mx);
                    const float p1 = __expf(s[n][2 * hf + 1] - mx);
                    s[n][2 * hf] = p0; s[n][2 * hf + 1] = p1;
                    ls += p0 + p1;
                }
                lrow[hf] += ls;
                mrow[hf] = mx;
            }

            // O += P V
#pragma unroll
            for (int ks = 0; ks < 4; ks++) {
                uint32_t pf[4];
#pragma unroll
                for (int q2 = 0; q2 < 2; q2++) {
                    const float* pv = s[2 * ks + q2];
                    pf[q2 * 2]     = pack_f16(pv[0], pv[1]);
                    pf[q2 * 2 + 1] = pack_f16(pv[2], pv[3]);
                }
#pragma unroll
                for (int np = 0; np < 4; np++) {
                    uint32_t vf[4];
                    const uint32_t va = vbse + (ks * 16 + v_row) * AROWB + np * 32 + v_coff;
                    LDMATRIX_X4_T(vf[0], vf[1], vf[2], vf[3], va);
                    uint32_t v0[2] = {vf[0], vf[1]}, v1[2] = {vf[2], vf[3]};
                    MMA_F16(o[2 * np],     pf, v0);
                    MMA_F16(o[2 * np + 1], pf, v1);
                }
            }
        }
        __syncthreads();
    }

    // finalize
    float inv[2];
#pragma unroll
    for (int hf = 0; hf < 2; hf++) {
        float l = lrow[hf];
        l += __shfl_xor_sync(0xffffffffu, l, 1);
        l += __shfl_xor_sync(0xffffffffu, l, 2);
        inv[hf] = 1.0f / l;
    }
    const int row0 = qbase + (lane >> 2);
    const int colb = h * HD + (lane & 3) * 2;
#pragma unroll
    for (int hf = 0; hf < 2; hf++) {
        const size_t rof = (size_t)(bS + row0 + 8 * hf) * DD;
#pragma unroll
        for (int n = 0; n < 8; n++)
            *(uint32_t*)(O + rof + colb + n * 8) =
                pack_f16(o[n][2 * hf] * inv[hf], o[n][2 * hf + 1] * inv[hf]);
    }
}

// ---------------------------------------------------------------------------
extern "C" void kernel_launch(void* const* d_in, const int* in_sizes, int n_in,
                              void* d_out, int out_size)
{
    const float* hidden   = (const float*)d_in[0];
    const float* c_attn_w = (const float*)d_in[1];
    const float* c_attn_b = (const float*)d_in[2];
    const float* c_proj_w = (const float*)d_in[3];
    const float* c_proj_b = (const float*)d_in[4];
    float* out = (float*)d_out;

    __half *qkv, *x, *a, *wq, *wp;
    cudaGetSymbolAddress((void**)&qkv, g_qkv);
    cudaGetSymbolAddress((void**)&x,   g_x);
    cudaGetSymbolAddress((void**)&a,   g_a);
    cudaGetSymbolAddress((void**)&wq,  g_wq);
    cudaGetSymbolAddress((void**)&wp,  g_wp);

    cudaFuncSetAttribute(gemm_mma, cudaFuncAttributeMaxDynamicSharedMemorySize, GSMEM);
    cudaFuncSetAttribute(attn_mma, cudaFuncAttributeMaxDynamicSharedMemorySize, ASMEM);

    wt_h<<<dim3(D3 / 32, DD / 32), dim3(32, 8)>>>(c_attn_w, wq, DD, D3);
    wt_h<<<dim3(DD / 32, DD / 32), dim3(32, 8)>>>(c_proj_w, wp, DD, DD);

    {
        const int n4 = NT * DD / 4;
        act_h<<<(n4 + 255) / 256, 256>>>((const float4*)hidden, (uint2*)x, n4);
    }

    // 1) QKV projection -> f16
    gemm_mma<<<dim3(D3 / 128, NT / 256), 512, GSMEM>>>(
        x, wq, c_attn_b, nullptr, qkv, NT, D3, DD);

    // 2) causal flash attention -> f16
    attn_mma<<<dim3(SS / 128, BB * HH), 256, ASMEM>>>(qkv, a);

    // 3) output projection -> fp32
    gemm_mma<<<dim3(DD / 128, NT / 256), 512, GSMEM>>>(
        a, wp, c_proj_b, out, nullptr, NT, DD, DD);
}

// round 8
// speedup vs baseline: 2.4997x; 1.0875x over previous
#include <cuda_runtime.h>
#include <cuda_fp16.h>
#include <cstdint>

// Problem constants
#define BB 4
#define SS 2048
#define DD 1024
#define HH 16
#define HD 64
#define NT (BB * SS)        // 8192 tokens
#define D3 (3 * DD)         // 3072

#define WSC 64.0f           // weight scale 2^6
#define IWSC (1.0f / 64.0f)

// ---------------------------------------------------------------------------
// Scratch (device globals — no runtime allocation)
// ---------------------------------------------------------------------------
static __device__ __half g_qkv[(size_t)NT * D3];
static __device__ __half g_x  [(size_t)NT * DD];
static __device__ __half g_a  [(size_t)NT * DD];
static __device__ __half g_wq [(size_t)D3 * DD];   // c_attn_w^T *64 [N][K]
static __device__ __half g_wp [(size_t)DD * DD];

// ---------------------------------------------------------------------------
__device__ __forceinline__ uint32_t smem_u32(const void* p) {
    uint32_t a;
    asm("{ .reg .u64 t; cvta.to.shared.u64 t, %1; cvt.u32.u64 %0, t; }" : "=r"(a) : "l"(p));
    return a;
}

#define CP_ASYNC16(saddr, gptr) \
    asm volatile("cp.async.cg.shared.global [%0], [%1], 16;" :: "r"(saddr), "l"(gptr) : "memory")
#define CP_COMMIT()  asm volatile("cp.async.commit_group;" ::: "memory")
#define CP_WAIT0()   asm volatile("cp.async.wait_group 0;" ::: "memory")
#define CP_WAIT1()   asm volatile("cp.async.wait_group 1;" ::: "memory")
#define CP_WAIT2()   asm volatile("cp.async.wait_group 2;" ::: "memory")

#define LDMATRIX_X4(r0, r1, r2, r3, addr) \
    asm volatile("ldmatrix.sync.aligned.m8n8.x4.shared.b16 {%0,%1,%2,%3}, [%4];" \
        : "=r"(r0), "=r"(r1), "=r"(r2), "=r"(r3) : "r"(addr))

#define LDMATRIX_X4_T(r0, r1, r2, r3, addr) \
    asm volatile("ldmatrix.sync.aligned.m8n8.x4.trans.shared.b16 {%0,%1,%2,%3}, [%4];" \
        : "=r"(r0), "=r"(r1), "=r"(r2), "=r"(r3) : "r"(addr))

#define MMA_F16(c, a, b) \
    asm volatile("mma.sync.aligned.m16n8k16.row.col.f32.f16.f16.f32 " \
        "{%0,%1,%2,%3}, {%4,%5,%6,%7}, {%8,%9}, {%0,%1,%2,%3};" \
        : "+f"((c)[0]), "+f"((c)[1]), "+f"((c)[2]), "+f"((c)[3]) \
        : "r"((a)[0]), "r"((a)[1]), "r"((a)[2]), "r"((a)[3]), "r"((b)[0]), "r"((b)[1]))

__device__ __forceinline__ uint32_t pack_f16(float a, float b) {
    __half2 t = __floats2half2_rn(a, b);
    return *reinterpret_cast<uint32_t*>(&t);
}

// ---------------------------------------------------------------------------
// Conversion kernels
// ---------------------------------------------------------------------------
__global__ void act_h(const float4* __restrict__ x, uint2* __restrict__ o, int n4) {
    int i = blockIdx.x * blockDim.x + threadIdx.x;
    if (i >= n4) return;
    float4 v = x[i];
    uint2 r;
    r.x = pack_f16(v.x, v.y);
    r.y = pack_f16(v.z, v.w);
    o[i] = r;
}

__global__ void wt_h(const float* __restrict__ W, __half* __restrict__ o, int K, int N) {
    __shared__ float t[32][33];
    const int kb = blockIdx.y * 32, nb = blockIdx.x * 32;
    const int tx = threadIdx.x, ty = threadIdx.y;
#pragma unroll
    for (int i = 0; i < 32; i += 8)
        t[ty + i][tx] = W[(size_t)(kb + ty + i) * N + nb + tx];
    __syncthreads();
#pragma unroll
    for (int i = 0; i < 32; i += 8)
        o[(size_t)(nb + ty + i) * K + kb + tx] = __float2half_rn(t[tx][ty + i] * WSC);
}

// ---------------------------------------------------------------------------
// f16 HMMA GEMM v3: C[M,N] = A[M,K] @ (B[N,K])^T * (1/64) + bias
// CTA tile 128(M) x 256(N), 256 threads = 8 warps (2x4), warp tile 64x64.
// BK=64 per stage, 4-stage cp.async ring, ONE barrier per stage.
// ---------------------------------------------------------------------------
#define GROWB 144                      // 128B row + 16B pad
#define GATILE (128 * GROWB)           // 18432
#define GBTILE (256 * GROWB)           // 36864
#define GSTAGE (GATILE + GBTILE)       // 55296
#define GSMEM  (4 * GSTAGE)            // 221184

extern __shared__ char g_dsmem[];

__global__ void __launch_bounds__(256) gemm_mma(
    const __half* __restrict__ A, const __half* __restrict__ B,
    const float* __restrict__ bias, float* __restrict__ Cf,
    __half* __restrict__ Ch, int M, int N, int K)
{
    const int tid  = threadIdx.x;
    const int wid  = tid >> 5;
    const int lane = tid & 31;
    const int wm   = wid >> 2;        // 0..1  (64 M-rows each)
    const int wn   = wid & 3;         // 0..3  (64 N-cols each)
    const int bm = blockIdx.y, bn = blockIdx.x;

    const __half* Ab = A + (size_t)(bm * 128) * K;
    const __half* Bb = B + (size_t)(bn * 256) * K;

    const uint32_t sb = smem_u32(g_dsmem);

    float acc[4][8][4];
#pragma unroll
    for (int i = 0; i < 4; i++)
#pragma unroll
        for (int j = 0; j < 8; j++)
#pragma unroll
            for (int v = 0; v < 4; v++) acc[i][j][v] = 0.0f;

    const int NS = K >> 6;            // 16 stages of K=64

    // stage = 3072 x 16B chunks: A 128 rows x 8, B 256 rows x 8; 12 per thread
    auto load_stage = [&](int s, int buf) {
        const int k0 = s << 6;
        const uint32_t base = sb + buf * GSTAGE;
#pragma unroll
        for (int i = 0; i < 12; i++) {
            const int idx = i * 256 + tid;
            if (idx < 1024) {
                const int r = idx >> 3, c = idx & 7;
                CP_ASYNC16(base + r * GROWB + c * 16, Ab + (size_t)r * K + k0 + c * 8);
            } else {
                const int j = idx - 1024;
                const int r = j >> 3, c = j & 7;
                CP_ASYNC16(base + GATILE + r * GROWB + c * 16, Bb + (size_t)r * K + k0 + c * 8);
            }
        }
        CP_COMMIT();
    };

    load_stage(0, 0);
    load_stage(1, 1);
    load_stage(2, 2);

    const int a_row  = (lane & 15);
    const int a_koff = (lane >> 4) * 16;
    const int b_blk  = lane >> 3;
    const int b_row8 = lane & 7;
    const int b_noff = ((b_blk >> 1) << 3) + b_row8;
    const int b_koff = (b_blk & 1) * 16;

    for (int s = 0; s < NS; s++) {
        if (s <= NS - 3)      CP_WAIT2();
        else if (s == NS - 2) CP_WAIT1();
        else                  CP_WAIT0();
        __syncthreads();
        // load stage s+3 into buf (s+3)&3 == (s-1)&3 — its compute finished
        // before the barrier above, so no second barrier is needed.
        if (s + 3 < NS) load_stage(s + 3, (s + 3) & 3);

        const uint32_t st = sb + (s & 3) * GSTAGE;
#pragma unroll
        for (int ks = 0; ks < 4; ks++) {
            const int kb = ks * 32;

            uint32_t af[4][4], bf[8][2];
#pragma unroll
            for (int mt = 0; mt < 4; mt++) {
                const uint32_t ar = st + (wm * 64 + mt * 16 + a_row) * GROWB + kb + a_koff;
                LDMATRIX_X4(af[mt][0], af[mt][1], af[mt][2], af[mt][3], ar);
            }
#pragma unroll
            for (int p = 0; p < 4; p++) {
                const uint32_t br = st + GATILE +
                    (wn * 64 + p * 16 + b_noff) * GROWB + kb + b_koff;
                LDMATRIX_X4(bf[2 * p][0], bf[2 * p][1], bf[2 * p + 1][0], bf[2 * p + 1][1], br);
            }
#pragma unroll
            for (int mt = 0; mt < 4; mt++)
#pragma unroll
                for (int nt = 0; nt < 8; nt++)
                    MMA_F16(acc[mt][nt], af[mt], bf[nt]);
        }
    }

    const int r0 = bm * 128 + wm * 64 + (lane >> 2);
    const int c0 = bn * 256 + wn * 64 + (lane & 3) * 2;
    if (Cf) {
#pragma unroll
        for (int mt = 0; mt < 4; mt++)
#pragma unroll
            for (int nt = 0; nt < 8; nt++) {
                const int row = r0 + mt * 16;
                const int col = c0 + nt * 8;
                float2 o0, o1;
                o0.x = acc[mt][nt][0] * IWSC + bias[col];
                o0.y = acc[mt][nt][1] * IWSC + bias[col + 1];
                o1.x = acc[mt][nt][2] * IWSC + bias[col];
                o1.y = acc[mt][nt][3] * IWSC + bias[col + 1];
                *(float2*)(Cf + (size_t)row * N + col) = o0;
                *(float2*)(Cf + (size_t)(row + 8) * N + col) = o1;
            }
    } else {
#pragma unroll
        for (int mt = 0; mt < 4; mt++)
#pragma unroll
            for (int nt = 0; nt < 8; nt++) {
                const int row = r0 + mt * 16;
                const int col = c0 + nt * 8;
                const float b0 = bias[col], b1 = bias[col + 1];
                *(uint32_t*)(Ch + (size_t)row * N + col) =
                    pack_f16(acc[mt][nt][0] * IWSC + b0, acc[mt][nt][1] * IWSC + b1);
                *(uint32_t*)(Ch + (size_t)(row + 8) * N + col) =
                    pack_f16(acc[mt][nt][2] * IWSC + b0, acc[mt][nt][3] * IWSC + b1);
            }
    }
}

// ---------------------------------------------------------------------------
// Tensor-core causal flash attention (unchanged from R7).
// ---------------------------------------------------------------------------
#define AROWB 144
#define ATILE (64 * AROWB)
#define ASTAGE (2 * ATILE)
#define ASMEM (2 * ASTAGE)

__global__ void __launch_bounds__(256) attn_mma(
    const __half* __restrict__ QKV, __half* __restrict__ O)
{
    const int tid  = threadIdx.x;
    const int wid  = tid >> 5;
    const int lane = tid & 31;
    const int qtile = (gridDim.x - 1) - blockIdx.x;
    const int bh = blockIdx.y;
    const int b  = bh >> 4;
    const int h  = bh & 15;
    const int bS = b * SS;
    const int qbase = qtile * 128 + wid * 16;

    const uint32_t sb = smem_u32(g_dsmem);

#pragma unroll
    for (int i = 0; i < 4; i++) {
        const int idx = i * 256 + tid;
        const int r = idx >> 3, c = idx & 7;
        const size_t g = (size_t)(bS + qtile * 128 + r) * D3 + h * HD + c * 8;
        CP_ASYNC16(sb + r * AROWB + c * 16, QKV + g);
    }
    CP_COMMIT();
    CP_WAIT0();
    __syncthreads();

    uint32_t qf[4][4];
    const int a_row  = lane & 15;
    const int a_koff = (lane >> 4) * 16;
    {
        const uint32_t qr = sb + (wid * 16 + a_row) * AROWB + a_koff;
#pragma unroll
        for (int ks = 0; ks < 4; ks++)
            LDMATRIX_X4(qf[ks][0], qf[ks][1], qf[ks][2], qf[ks][3], qr + ks * 32);
    }
    __syncthreads();

    auto load_kv = [&](int kt, int buf) {
        const int k0 = kt * 64;
        const uint32_t base = sb + buf * ASTAGE;
#pragma unroll
        for (int i = 0; i < 4; i++) {
            const int idx  = i * 256 + tid;
            const int tile = idx >> 9;
            const int r    = (idx >> 3) & 63;
            const int c    = idx & 7;
            const size_t g = (size_t)(bS + k0 + r) * D3 +
                             (tile ? 2 * DD : DD) + h * HD + c * 8;
            CP_ASYNC16(base + tile * ATILE + r * AROWB + c * 16, QKV + g);
        }
        CP_COMMIT();
    };

    float o[8][4];
#pragma unroll
    for (int n = 0; n < 8; n++)
#pragma unroll
        for (int j = 0; j < 4; j++) o[n][j] = 0.0f;
    float mrow[2] = {-1e30f, -1e30f};
    float lrow[2] = {0.0f, 0.0f};

    const int b_blk  = lane >> 3;
    const int b_row8 = lane & 7;
    const int b_noff = ((b_blk >> 1) << 3) + b_row8;
    const int b_koff = (b_blk & 1) * 16;
    const int v_row  = lane & 15;
    const int v_coff = ((lane >> 4) & 1) * 16;

    const int ntl = 2 * qtile + 2;
    load_kv(0, 0);

    for (int kt = 0; kt < ntl; kt++) {
        const int buf = kt & 1;
        const int k0 = kt * 64;
        if (kt + 1 < ntl) { load_kv(kt + 1, buf ^ 1); CP_WAIT1(); }
        else              { CP_WAIT0(); }
        __syncthreads();

        if (k0 <= qbase + 15) {
            const uint32_t kbse = sb + buf * ASTAGE;
            const uint32_t vbse = kbse + ATILE;

            float s[8][4];
#pragma unroll
            for (int n = 0; n < 8; n++)
#pragma unroll
                for (int j = 0; j < 4; j++) s[n][j] = 0.0f;

#pragma unroll
            for (int p = 0; p < 4; p++) {
#pragma unroll
                for (int ks = 0; ks < 4; ks++) {
                    uint32_t kf[4];
                    const uint32_t ar = kbse + (p * 16 + b_noff) * AROWB + ks * 32 + b_koff;
                    LDMATRIX_X4(kf[0], kf[1], kf[2], kf[3], ar);
                    uint32_t b0[2] = {kf[0], kf[1]}, b1[2] = {kf[2], kf[3]};
                    MMA_F16(s[2 * p],     qf[ks], b0);
                    MMA_F16(s[2 * p + 1], qf[ks], b1);
                }
            }

            const bool need_mask = (k0 + 63 > qbase);
            const int row0 = qbase + (lane >> 2);
            const int colb = k0 + (lane & 3) * 2;
#pragma unroll
            for (int hf = 0; hf < 2; hf++) {
                const int row = row0 + 8 * hf;
                float mx = mrow[hf];
#pragma unroll
                for (int n = 0; n < 8; n++) {
                    float v0 = s[n][2 * hf]     * 0.125f;
                    float v1 = s[n][2 * hf + 1] * 0.125f;
                    if (need_mask) {
                        const int col = colb + 8 * n;
                        if (col > row)     v0 = -1e30f;
                        if (col + 1 > row) v1 = -1e30f;
                    }
                    s[n][2 * hf] = v0; s[n][2 * hf + 1] = v1;
                    mx = fmaxf(mx, fmaxf(v0, v1));
                }
                mx = fmaxf(mx, __shfl_xor_sync(0xffffffffu, mx, 1));
                mx = fmaxf(mx, __shfl_xor_sync(0xffffffffu, mx, 2));
                const float alpha = __expf(mrow[hf] - mx);
                lrow[hf] *= alpha;
#pragma unroll
                for (int n = 0; n < 8; n++) {
                    o[n][2 * hf]     *= alpha;
                    o[n][2 * hf + 1] *= alpha;
                }
                float ls = 0.0f;
#pragma unroll
                for (int n = 0; n < 8; n++) {
                    const float p0 = __expf(s[n][2 * hf]     - mx);
                    const float p1 = __expf(s[n][2 * hf + 1] - mx);
                    s[n][2 * hf] = p0; s[n][2 * hf + 1] = p1;
                    ls += p0 + p1;
                }
                lrow[hf] += ls;
                mrow[hf] = mx;
            }

#pragma unroll
            for (int ks = 0; ks < 4; ks++) {
                uint32_t pf[4];
#pragma unroll
                for (int q2 = 0; q2 < 2; q2++) {
                    const float* pv = s[2 * ks + q2];
                    pf[q2 * 2]     = pack_f16(pv[0], pv[1]);
                    pf[q2 * 2 + 1] = pack_f16(pv[2], pv[3]);
                }
#pragma unroll
                for (int np = 0; np < 4; np++) {
                    uint32_t vf[4];
                    const uint32_t va = vbse + (ks * 16 + v_row) * AROWB + np * 32 + v_coff;
                    LDMATRIX_X4_T(vf[0], vf[1], vf[2], vf[3], va);
                    uint32_t v0[2] = {vf[0], vf[1]}, v1[2] = {vf[2], vf[3]};
                    MMA_F16(o[2 * np],     pf, v0);
                    MMA_F16(o[2 * np + 1], pf, v1);
                }
            }
        }
        __syncthreads();
    }

    float inv[2];
#pragma unroll
    for (int hf = 0; hf < 2; hf++) {
        float l = lrow[hf];
        l += __shfl_xor_sync(0xffffffffu, l, 1);
        l += __shfl_xor_sync(0xffffffffu, l, 2);
        inv[hf] = 1.0f / l;
    }
    const int row0 = qbase + (lane >> 2);
    const int colb = h * HD + (lane & 3) * 2;
#pragma unroll
    for (int hf = 0; hf < 2; hf++) {
        const size_t rof = (size_t)(bS + row0 + 8 * hf) * DD;
#pragma unroll
        for (int n = 0; n < 8; n++)
            *(uint32_t*)(O + rof + colb + n * 8) =
                pack_f16(o[n][2 * hf] * inv[hf], o[n][2 * hf + 1] * inv[hf]);
    }
}

// ---------------------------------------------------------------------------
extern "C" void kernel_launch(void* const* d_in, const int* in_sizes, int n_in,
                              void* d_out, int out_size)
{
    const float* hidden   = (const float*)d_in[0];
    const float* c_attn_w = (const float*)d_in[1];
    const float* c_attn_b = (const float*)d_in[2];
    const float* c_proj_w = (const float*)d_in[3];
    const float* c_proj_b = (const float*)d_in[4];
    float* out = (float*)d_out;

    __half *qkv, *x, *a, *wq, *wp;
    cudaGetSymbolAddress((void**)&qkv, g_qkv);
    cudaGetSymbolAddress((void**)&x,   g_x);
    cudaGetSymbolAddress((void**)&a,   g_a);
    cudaGetSymbolAddress((void**)&wq,  g_wq);
    cudaGetSymbolAddress((void**)&wp,  g_wp);

    cudaFuncSetAttribute(gemm_mma, cudaFuncAttributeMaxDynamicSharedMemorySize, GSMEM);
    cudaFuncSetAttribute(attn_mma, cudaFuncAttributeMaxDynamicSharedMemorySize, ASMEM);

    wt_h<<<dim3(D3 / 32, DD / 32), dim3(32, 8)>>>(c_attn_w, wq, DD, D3);
    wt_h<<<dim3(DD / 32, DD / 32), dim3(32, 8)>>>(c_proj_w, wp, DD, DD);

    {
        const int n4 = NT * DD / 4;
        act_h<<<(n4 + 255) / 256, 256>>>((const float4*)hidden, (uint2*)x, n4);
    }

    // 1) QKV projection -> f16
    gemm_mma<<<dim3(D3 / 256, NT / 128), 256, GSMEM>>>(
        x, wq, c_attn_b, nullptr, qkv, NT, D3, DD);

    // 2) causal flash attention -> f16
    attn_mma<<<dim3(SS / 128, BB * HH), 256, ASMEM>>>(qkv, a);

    // 3) output projection -> fp32
    gemm_mma<<<dim3(DD / 256, NT / 128), 256, GSMEM>>>(
        a, wp, c_proj_b, out, nullptr, NT, DD, DD);
}

// round 9
// speedup vs baseline: 2.7068x; 1.0828x over previous
#include <cuda_runtime.h>
#include <cuda_fp16.h>
#include <cstdint>

// Problem constants
#define BB 4
#define SS 2048
#define DD 1024
#define HH 16
#define HD 64
#define NT (BB * SS)        // 8192 tokens
#define D3 (3 * DD)         // 3072

#define WSC 64.0f           // weight scale 2^6
#define IWSC (1.0f / 64.0f)

// ---------------------------------------------------------------------------
// Scratch (device globals — no runtime allocation)
// ---------------------------------------------------------------------------
static __device__ __half g_qkv[(size_t)NT * D3];
static __device__ __half g_x  [(size_t)NT * DD];
static __device__ __half g_a  [(size_t)NT * DD];
static __device__ __half g_wq [(size_t)D3 * DD];   // c_attn_w^T *64 [N][K]
static __device__ __half g_wp [(size_t)DD * DD];

// ---------------------------------------------------------------------------
__device__ __forceinline__ uint32_t smem_u32(const void* p) {
    uint32_t a;
    asm("{ .reg .u64 t; cvta.to.shared.u64 t, %1; cvt.u32.u64 %0, t; }" : "=r"(a) : "l"(p));
    return a;
}

#define CP_ASYNC16(saddr, gptr) \
    asm volatile("cp.async.cg.shared.global [%0], [%1], 16;" :: "r"(saddr), "l"(gptr) : "memory")
#define CP_COMMIT()  asm volatile("cp.async.commit_group;" ::: "memory")
#define CP_WAIT0()   asm volatile("cp.async.wait_group 0;" ::: "memory")
#define CP_WAIT1()   asm volatile("cp.async.wait_group 1;" ::: "memory")

#define LDMATRIX_X4(r0, r1, r2, r3, addr) \
    asm volatile("ldmatrix.sync.aligned.m8n8.x4.shared.b16 {%0,%1,%2,%3}, [%4];" \
        : "=r"(r0), "=r"(r1), "=r"(r2), "=r"(r3) : "r"(addr))

#define LDMATRIX_X4_T(r0, r1, r2, r3, addr) \
    asm volatile("ldmatrix.sync.aligned.m8n8.x4.trans.shared.b16 {%0,%1,%2,%3}, [%4];" \
        : "=r"(r0), "=r"(r1), "=r"(r2), "=r"(r3) : "r"(addr))

#define MMA_F16(c, a, b) \
    asm volatile("mma.sync.aligned.m16n8k16.row.col.f32.f16.f16.f32 " \
        "{%0,%1,%2,%3}, {%4,%5,%6,%7}, {%8,%9}, {%0,%1,%2,%3};" \
        : "+f"((c)[0]), "+f"((c)[1]), "+f"((c)[2]), "+f"((c)[3]) \
        : "r"((a)[0]), "r"((a)[1]), "r"((a)[2]), "r"((a)[3]), "r"((b)[0]), "r"((b)[1]))

__device__ __forceinline__ uint32_t pack_f16(float a, float b) {
    __half2 t = __floats2half2_rn(a, b);
    return *reinterpret_cast<uint32_t*>(&t);
}

// ---------------------------------------------------------------------------
// Conversion kernels
// ---------------------------------------------------------------------------
__global__ void act_h(const float4* __restrict__ x, uint2* __restrict__ o, int n4) {
    int i = blockIdx.x * blockDim.x + threadIdx.x;
    if (i >= n4) return;
    float4 v = x[i];
    uint2 r;
    r.x = pack_f16(v.x, v.y);
    r.y = pack_f16(v.z, v.w);
    o[i] = r;
}

__global__ void wt_h(const float* __restrict__ W, __half* __restrict__ o, int K, int N) {
    __shared__ float t[32][33];
    const int kb = blockIdx.y * 32, nb = blockIdx.x * 32;
    const int tx = threadIdx.x, ty = threadIdx.y;
#pragma unroll
    for (int i = 0; i < 32; i += 8)
        t[ty + i][tx] = W[(size_t)(kb + ty + i) * N + nb + tx];
    __syncthreads();
#pragma unroll
    for (int i = 0; i < 32; i += 8)
        o[(size_t)(nb + ty + i) * K + kb + tx] = __float2half_rn(t[tx][ty + i] * WSC);
}

// ---------------------------------------------------------------------------
// f16 HMMA GEMM v4: C[M,N] = A[M,K] @ (B[N,K])^T * (1/64) + bias
// CTA tile 128x128, 128 threads = 4 warps (2x2), warp tile 64x64.
// BK=64, 3-stage cp.async ring, ONE barrier per stage, 2 CTAs per SM
// (independent barrier domains hide each other's stalls).
// ---------------------------------------------------------------------------
#define GROWB 144                      // 128B row + 16B pad
#define GATILE (128 * GROWB)           // 18432
#define GSTAGE (2 * GATILE)            // A|B = 36864
#define GSMEM  (3 * GSTAGE)            // 110592

extern __shared__ char g_dsmem[];

__global__ void __launch_bounds__(128, 2) gemm_mma(
    const __half* __restrict__ A, const __half* __restrict__ B,
    const float* __restrict__ bias, float* __restrict__ Cf,
    __half* __restrict__ Ch, int M, int N, int K)
{
    const int tid  = threadIdx.x;
    const int wid  = tid >> 5;
    const int lane = tid & 31;
    const int wm   = wid >> 1;        // 0..1  (64 M-rows)
    const int wn   = wid & 1;         // 0..1  (64 N-cols)
    const int bm = blockIdx.y, bn = blockIdx.x;

    const __half* Ab = A + (size_t)(bm * 128) * K;
    const __half* Bb = B + (size_t)(bn * 128) * K;

    const uint32_t sb = smem_u32(g_dsmem);

    float acc[4][8][4];
#pragma unroll
    for (int i = 0; i < 4; i++)
#pragma unroll
        for (int j = 0; j < 8; j++)
#pragma unroll
            for (int v = 0; v < 4; v++) acc[i][j][v] = 0.0f;

    const int NS = K >> 6;            // 16 stages of K=64

    // stage = 2048 x 16B chunks (A 128x8, B 128x8); 16 per thread
    auto load_stage = [&](int s, int buf) {
        const int k0 = s << 6;
        const uint32_t base = sb + buf * GSTAGE;
#pragma unroll
        for (int i = 0; i < 8; i++) {
            const int idx = i * 128 + tid;
            const int r = idx >> 3, c = idx & 7;
            CP_ASYNC16(base + r * GROWB + c * 16, Ab + (size_t)r * K + k0 + c * 8);
        }
#pragma unroll
        for (int i = 0; i < 8; i++) {
            const int idx = i * 128 + tid;
            const int r = idx >> 3, c = idx & 7;
            CP_ASYNC16(base + GATILE + r * GROWB + c * 16, Bb + (size_t)r * K + k0 + c * 8);
        }
        CP_COMMIT();
    };

    load_stage(0, 0);
    load_stage(1, 1);

    const int a_row  = (lane & 15);
    const int a_koff = (lane >> 4) * 16;
    const int b_blk  = lane >> 3;
    const int b_row8 = lane & 7;
    const int b_noff = ((b_blk >> 1) << 3) + b_row8;
    const int b_koff = (b_blk & 1) * 16;

    for (int s = 0; s < NS; s++) {
        if (s < NS - 1) CP_WAIT1();
        else            CP_WAIT0();
        __syncthreads();
        // buffer (s+2)%3 == (s-1)%3 finished compute before the barrier above
        if (s + 2 < NS) load_stage(s + 2, (s + 2) % 3);

        const uint32_t st = sb + (s % 3) * GSTAGE;
#pragma unroll
        for (int ks = 0; ks < 4; ks++) {
            const int kb = ks * 32;

            uint32_t af[4][4], bf[8][2];
#pragma unroll
            for (int mt = 0; mt < 4; mt++) {
                const uint32_t ar = st + (wm * 64 + mt * 16 + a_row) * GROWB + kb + a_koff;
                LDMATRIX_X4(af[mt][0], af[mt][1], af[mt][2], af[mt][3], ar);
            }
#pragma unroll
            for (int p = 0; p < 4; p++) {
                const uint32_t br = st + GATILE +
                    (wn * 64 + p * 16 + b_noff) * GROWB + kb + b_koff;
                LDMATRIX_X4(bf[2 * p][0], bf[2 * p][1], bf[2 * p + 1][0], bf[2 * p + 1][1], br);
            }
#pragma unroll
            for (int mt = 0; mt < 4; mt++)
#pragma unroll
                for (int nt = 0; nt < 8; nt++)
                    MMA_F16(acc[mt][nt], af[mt], bf[nt]);
        }
    }

    const int r0 = bm * 128 + wm * 64 + (lane >> 2);
    const int c0 = bn * 128 + wn * 64 + (lane & 3) * 2;
    if (Cf) {
#pragma unroll
        for (int mt = 0; mt < 4; mt++)
#pragma unroll
            for (int nt = 0; nt < 8; nt++) {
                const int row = r0 + mt * 16;
                const int col = c0 + nt * 8;
                float2 o0, o1;
                o0.x = acc[mt][nt][0] * IWSC + bias[col];
                o0.y = acc[mt][nt][1] * IWSC + bias[col + 1];
                o1.x = acc[mt][nt][2] * IWSC + bias[col];
                o1.y = acc[mt][nt][3] * IWSC + bias[col + 1];
                *(float2*)(Cf + (size_t)row * N + col) = o0;
                *(float2*)(Cf + (size_t)(row + 8) * N + col) = o1;
            }
    } else {
#pragma unroll
        for (int mt = 0; mt < 4; mt++)
#pragma unroll
            for (int nt = 0; nt < 8; nt++) {
                const int row = r0 + mt * 16;
                const int col = c0 + nt * 8;
                const float b0 = bias[col], b1 = bias[col + 1];
                *(uint32_t*)(Ch + (size_t)row * N + col) =
                    pack_f16(acc[mt][nt][0] * IWSC + b0, acc[mt][nt][1] * IWSC + b1);
                *(uint32_t*)(Ch + (size_t)(row + 8) * N + col) =
                    pack_f16(acc[mt][nt][2] * IWSC + b0, acc[mt][nt][3] * IWSC + b1);
            }
    }
}

// ---------------------------------------------------------------------------
// Tensor-core causal flash attention (unchanged from R8).
// ---------------------------------------------------------------------------
#define AROWB 144
#define ATILE (64 * AROWB)
#define ASTAGE (2 * ATILE)
#define ASMEM (2 * ASTAGE)

__global__ void __launch_bounds__(256) attn_mma(
    const __half* __restrict__ QKV, __half* __restrict__ O)
{
    const int tid  = threadIdx.x;
    const int wid  = tid >> 5;
    const int lane = tid & 31;
    const int qtile = (gridDim.x - 1) - blockIdx.x;
    const int bh = blockIdx.y;
    const int b  = bh >> 4;
    const int h  = bh & 15;
    const int bS = b * SS;
    const int qbase = qtile * 128 + wid * 16;

    const uint32_t sb = smem_u32(g_dsmem);

#pragma unroll
    for (int i = 0; i < 4; i++) {
        const int idx = i * 256 + tid;
        const int r = idx >> 3, c = idx & 7;
        const size_t g = (size_t)(bS + qtile * 128 + r) * D3 + h * HD + c * 8;
        CP_ASYNC16(sb + r * AROWB + c * 16, QKV + g);
    }
    CP_COMMIT();
    CP_WAIT0();
    __syncthreads();

    uint32_t qf[4][4];
    const int a_row  = lane & 15;
    const int a_koff = (lane >> 4) * 16;
    {
        const uint32_t qr = sb + (wid * 16 + a_row) * AROWB + a_koff;
#pragma unroll
        for (int ks = 0; ks < 4; ks++)
            LDMATRIX_X4(qf[ks][0], qf[ks][1], qf[ks][2], qf[ks][3], qr + ks * 32);
    }
    __syncthreads();

    auto load_kv = [&](int kt, int buf) {
        const int k0 = kt * 64;
        const uint32_t base = sb + buf * ASTAGE;
#pragma unroll
        for (int i = 0; i < 4; i++) {
            const int idx  = i * 256 + tid;
            const int tile = idx >> 9;
            const int r    = (idx >> 3) & 63;
            const int c    = idx & 7;
            const size_t g = (size_t)(bS + k0 + r) * D3 +
                             (tile ? 2 * DD : DD) + h * HD + c * 8;
            CP_ASYNC16(base + tile * ATILE + r * AROWB + c * 16, QKV + g);
        }
        CP_COMMIT();
    };

    float o[8][4];
#pragma unroll
    for (int n = 0; n < 8; n++)
#pragma unroll
        for (int j = 0; j < 4; j++) o[n][j] = 0.0f;
    float mrow[2] = {-1e30f, -1e30f};
    float lrow[2] = {0.0f, 0.0f};

    const int b_blk  = lane >> 3;
    const int b_row8 = lane & 7;
    const int b_noff = ((b_blk >> 1) << 3) + b_row8;
    const int b_koff = (b_blk & 1) * 16;
    const int v_row  = lane & 15;
    const int v_coff = ((lane >> 4) & 1) * 16;

    const int ntl = 2 * qtile + 2;
    load_kv(0, 0);

    for (int kt = 0; kt < ntl; kt++) {
        const int buf = kt & 1;
        const int k0 = kt * 64;
        if (kt + 1 < ntl) { load_kv(kt + 1, buf ^ 1); CP_WAIT1(); }
        else              { CP_WAIT0(); }
        __syncthreads();

        if (k0 <= qbase + 15) {
            const uint32_t kbse = sb + buf * ASTAGE;
            const uint32_t vbse = kbse + ATILE;

            float s[8][4];
#pragma unroll
            for (int n = 0; n < 8; n++)
#pragma unroll
                for (int j = 0; j < 4; j++) s[n][j] = 0.0f;

#pragma unroll
            for (int p = 0; p < 4; p++) {
#pragma unroll
                for (int ks = 0; ks < 4; ks++) {
                    uint32_t kf[4];
                    const uint32_t ar = kbse + (p * 16 + b_noff) * AROWB + ks * 32 + b_koff;
                    LDMATRIX_X4(kf[0], kf[1], kf[2], kf[3], ar);
                    uint32_t b0[2] = {kf[0], kf[1]}, b1[2] = {kf[2], kf[3]};
                    MMA_F16(s[2 * p],     qf[ks], b0);
                    MMA_F16(s[2 * p + 1], qf[ks], b1);
                }
            }

            const bool need_mask = (k0 + 63 > qbase);
            const int row0 = qbase + (lane >> 2);
            const int colb = k0 + (lane & 3) * 2;
#pragma unroll
            for (int hf = 0; hf < 2; hf++) {
                const int row = row0 + 8 * hf;
                float mx = mrow[hf];
#pragma unroll
                for (int n = 0; n < 8; n++) {
                    float v0 = s[n][2 * hf]     * 0.125f;
                    float v1 = s[n][2 * hf + 1] * 0.125f;
                    if (need_mask) {
                        const int col = colb + 8 * n;
                        if (col > row)     v0 = -1e30f;
                        if (col + 1 > row) v1 = -1e30f;
                    }
                    s[n][2 * hf] = v0; s[n][2 * hf + 1] = v1;
                    mx = fmaxf(mx, fmaxf(v0, v1));
                }
                mx = fmaxf(mx, __shfl_xor_sync(0xffffffffu, mx, 1));
                mx = fmaxf(mx, __shfl_xor_sync(0xffffffffu, mx, 2));
                const float alpha = __expf(mrow[hf] - mx);
                lrow[hf] *= alpha;
#pragma unroll
                for (int n = 0; n < 8; n++) {
                    o[n][2 * hf]     *= alpha;
                    o[n][2 * hf + 1] *= alpha;
                }
                float ls = 0.0f;
#pragma unroll
                for (int n = 0; n < 8; n++) {
                    const float p0 = __expf(s[n][2 * hf]     - mx);
                    const float p1 = __expf(s[n][2 * hf + 1] - mx);
                    s[n][2 * hf] = p0; s[n][2 * hf + 1] = p1;
                    ls += p0 + p1;
                }
                lrow[hf] += ls;
                mrow[hf] = mx;
            }

#pragma unroll
            for (int ks = 0; ks < 4; ks++) {
                uint32_t pf[4];
#pragma unroll
                for (int q2 = 0; q2 < 2; q2++) {
                    const float* pv = s[2 * ks + q2];
                    pf[q2 * 2]     = pack_f16(pv[0], pv[1]);
                    pf[q2 * 2 + 1] = pack_f16(pv[2], pv[3]);
                }
#pragma unroll
                for (int np = 0; np < 4; np++) {
                    uint32_t vf[4];
                    const uint32_t va = vbse + (ks * 16 + v_row) * AROWB + np * 32 + v_coff;
                    LDMATRIX_X4_T(vf[0], vf[1], vf[2], vf[3], va);
                    uint32_t v0[2] = {vf[0], vf[1]}, v1[2] = {vf[2], vf[3]};
                    MMA_F16(o[2 * np],     pf, v0);
                    MMA_F16(o[2 * np + 1], pf, v1);
                }
            }
        }
        __syncthreads();
    }

    float inv[2];
#pragma unroll
    for (int hf = 0; hf < 2; hf++) {
        float l = lrow[hf];
        l += __shfl_xor_sync(0xffffffffu, l, 1);
        l += __shfl_xor_sync(0xffffffffu, l, 2);
        inv[hf] = 1.0f / l;
    }
    const int row0 = qbase + (lane >> 2);
    const int colb = h * HD + (lane & 3) * 2;
#pragma unroll
    for (int hf = 0; hf < 2; hf++) {
        const size_t rof = (size_t)(bS + row0 + 8 * hf) * DD;
#pragma unroll
        for (int n = 0; n < 8; n++)
            *(uint32_t*)(O + rof + colb + n * 8) =
                pack_f16(o[n][2 * hf] * inv[hf], o[n][2 * hf + 1] * inv[hf]);
    }
}

// ---------------------------------------------------------------------------
extern "C" void kernel_launch(void* const* d_in, const int* in_sizes, int n_in,
                              void* d_out, int out_size)
{
    const float* hidden   = (const float*)d_in[0];
    const float* c_attn_w = (const float*)d_in[1];
    const float* c_attn_b = (const float*)d_in[2];
    const float* c_proj_w = (const float*)d_in[3];
    const float* c_proj_b = (const float*)d_in[4];
    float* out = (float*)d_out;

    __half *qkv, *x, *a, *wq, *wp;
    cudaGetSymbolAddress((void**)&qkv, g_qkv);
    cudaGetSymbolAddress((void**)&x,   g_x);
    cudaGetSymbolAddress((void**)&a,   g_a);
    cudaGetSymbolAddress((void**)&wq,  g_wq);
    cudaGetSymbolAddress((void**)&wp,  g_wp);

    cudaFuncSetAttribute(gemm_mma, cudaFuncAttributeMaxDynamicSharedMemorySize, GSMEM);
    cudaFuncSetAttribute(attn_mma, cudaFuncAttributeMaxDynamicSharedMemorySize, ASMEM);

    wt_h<<<dim3(D3 / 32, DD / 32), dim3(32, 8)>>>(c_attn_w, wq, DD, D3);
    wt_h<<<dim3(DD / 32, DD / 32), dim3(32, 8)>>>(c_proj_w, wp, DD, DD);

    {
        const int n4 = NT * DD / 4;
        act_h<<<(n4 + 255) / 256, 256>>>((const float4*)hidden, (uint2*)x, n4);
    }

    // 1) QKV projection -> f16
    gemm_mma<<<dim3(D3 / 128, NT / 128), 128, GSMEM>>>(
        x, wq, c_attn_b, nullptr, qkv, NT, D3, DD);

    // 2) causal flash attention -> f16
    attn_mma<<<dim3(SS / 128, BB * HH), 256, ASMEM>>>(qkv, a);

    // 3) output projection -> fp32
    gemm_mma<<<dim3(DD / 128, NT / 128), 128, GSMEM>>>(
        a, wp, c_proj_b, out, nullptr, NT, DD, DD);
}